// round 11
// baseline (speedup 1.0000x reference)
#include <cuda_runtime.h>
#include <cuda_fp16.h>
#include <math.h>
#include <stdint.h>

#define N_NODES 50000
#define N_EDGES 800000
#define N_GRAPHS 100

// ---------------- device scratch (no allocation allowed; 16B aligned) ----------------
__device__ __align__(16) int    d_cnt[N_NODES];      // stays 0 between calls (re-zeroed by pool_mlp)
__device__ __align__(16) float  d_dinv[N_NODES];
__device__ __align__(16) int    d_off[N_NODES];
__device__ __align__(16) int    d_cursor[N_NODES];
__device__ __align__(16) int    d_src[N_EDGES];
__device__ int d_gcur;                               // stays 0 between calls
__device__ __align__(16) __half d_x16[(size_t)N_NODES * 128]; // fp16 copy of x
__device__ __align__(16) __half d_w16[40960];                 // fp16 W1|W2|W3 images
__device__ __align__(16) __half d_t[(size_t)N_NODES * 128];   // fp16 gather buffer
__device__ __align__(16) __half d_hh[(size_t)N_NODES * 128];  // fp16 features

// ---------------- mma helpers ----------------
__device__ __forceinline__ uint32_t smem_u32(const void* p) {
    uint32_t a;
    asm("{ .reg .u64 t; cvta.to.shared.u64 t, %1; cvt.u32.u64 %0, t; }" : "=r"(a) : "l"(p));
    return a;
}
__device__ __forceinline__ void ldsm_x4(uint32_t& r0, uint32_t& r1, uint32_t& r2, uint32_t& r3,
                                        uint32_t addr) {
    asm volatile("ldmatrix.sync.aligned.m8n8.x4.shared.b16 {%0,%1,%2,%3}, [%4];"
                 : "=r"(r0), "=r"(r1), "=r"(r2), "=r"(r3) : "r"(addr));
}
__device__ __forceinline__ void ldsm_x4_t(uint32_t& r0, uint32_t& r1, uint32_t& r2, uint32_t& r3,
                                          uint32_t addr) {
    asm volatile("ldmatrix.sync.aligned.m8n8.x4.trans.shared.b16 {%0,%1,%2,%3}, [%4];"
                 : "=r"(r0), "=r"(r1), "=r"(r2), "=r"(r3) : "r"(addr));
}
__device__ __forceinline__ void mma16816(float* c, const uint32_t* a, uint32_t b0, uint32_t b1) {
    asm volatile("mma.sync.aligned.m16n8k16.row.col.f32.f16.f16.f32 "
                 "{%0,%1,%2,%3}, {%4,%5,%6,%7}, {%8,%9}, {%0,%1,%2,%3};"
                 : "+f"(c[0]), "+f"(c[1]), "+f"(c[2]), "+f"(c[3])
                 : "r"(a[0]), "r"(a[1]), "r"(a[2]), "r"(a[3]), "r"(b0), "r"(b1));
}

// ---------------- fp16 prep ----------------
__global__ void conv_x_kernel(const float* __restrict__ x, __half* __restrict__ x16) {
    size_t i = ((size_t)blockIdx.x * blockDim.x + threadIdx.x) * 8;
    if (i >= (size_t)N_NODES * 128) return;
    float4 a0 = *reinterpret_cast<const float4*>(x + i);
    float4 a1 = *reinterpret_cast<const float4*>(x + i + 4);
    uint4 o;
    __half2 h;
    h = __floats2half2_rn(a0.x, a0.y); o.x = *reinterpret_cast<uint32_t*>(&h);
    h = __floats2half2_rn(a0.z, a0.w); o.y = *reinterpret_cast<uint32_t*>(&h);
    h = __floats2half2_rn(a1.x, a1.y); o.z = *reinterpret_cast<uint32_t*>(&h);
    h = __floats2half2_rn(a1.z, a1.w); o.w = *reinterpret_cast<uint32_t*>(&h);
    *reinterpret_cast<uint4*>(x16 + i) = o;
}

__global__ void conv_w_kernel(const float* __restrict__ W1, const float* __restrict__ W2,
                              const float* __restrict__ W3, __half* __restrict__ w16) {
    int i = blockIdx.x * blockDim.x + threadIdx.x;
    if (i < 16384)      w16[i] = __float2half_rn(W1[i]);
    else if (i < 32768) w16[i] = __float2half_rn(W2[i - 16384]);
    else if (i < 40960) w16[i] = __float2half_rn(W3[i - 32768]);
}

// ---------------- CSR build (scan-free) ----------------
__global__ void count_kernel(const int* __restrict__ col, int* __restrict__ cnt) {
    int e2 = blockIdx.x * blockDim.x + threadIdx.x;
    int e = e2 * 2;
    if (e + 1 < N_EDGES) {
        int2 c = *reinterpret_cast<const int2*>(col + e);
        if ((unsigned)c.x < N_NODES) atomicAdd(cnt + c.x, 1);
        if ((unsigned)c.y < N_NODES) atomicAdd(cnt + c.y, 1);
    } else if (e < N_EDGES) {
        unsigned c = (unsigned)col[e];
        if (c < N_NODES) atomicAdd(cnt + c, 1);
    }
}

__global__ void assign_kernel(const int* __restrict__ cnt, int* __restrict__ off,
                              int* __restrict__ cursor, float* __restrict__ dinv,
                              int* __restrict__ gcur) {
    __shared__ int ws[32];
    __shared__ int s_base;
    int i = blockIdx.x * 1024 + threadIdx.x;
    int lane = threadIdx.x & 31, wid = threadIdx.x >> 5;
    int v = (i < N_NODES) ? cnt[i] : 0;
    int x = v;
    #pragma unroll
    for (int d = 1; d < 32; d <<= 1) {
        int y = __shfl_up_sync(0xffffffffu, x, d);
        if (lane >= d) x += y;
    }
    if (lane == 31) ws[wid] = x;
    __syncthreads();
    if (wid == 0) {
        int s = ws[lane];
        #pragma unroll
        for (int d = 1; d < 32; d <<= 1) {
            int y = __shfl_up_sync(0xffffffffu, s, d);
            if (lane >= d) s += y;
        }
        ws[lane] = s;
        if (lane == 31) s_base = atomicAdd(gcur, s);
    }
    __syncthreads();
    int excl = s_base + (wid ? ws[wid - 1] : 0) + x - v;
    if (i < N_NODES) {
        off[i] = excl;
        cursor[i] = excl;
        dinv[i] = rsqrtf((float)(v + 1));
    }
}

__global__ void fill_kernel(const int* __restrict__ row,
                            const int* __restrict__ col,
                            int* __restrict__ cursor, int* __restrict__ src) {
    int e2 = blockIdx.x * blockDim.x + threadIdx.x;
    int e = e2 * 2;
    if (e + 1 < N_EDGES) {
        int2 c = *reinterpret_cast<const int2*>(col + e);
        int2 r = *reinterpret_cast<const int2*>(row + e);
        if ((unsigned)c.x < N_NODES) {
            int pos = atomicAdd(cursor + c.x, 1);
            if ((unsigned)pos < N_EDGES) src[pos] = r.x;
        }
        if ((unsigned)c.y < N_NODES) {
            int pos = atomicAdd(cursor + c.y, 1);
            if ((unsigned)pos < N_EDGES) src[pos] = r.y;
        }
    } else if (e < N_EDGES) {
        unsigned c = (unsigned)col[e];
        if (c < N_NODES) {
            int pos = atomicAdd(cursor + c, 1);
            if ((unsigned)pos < N_EDGES) src[pos] = row[e];
        }
    }
}

// ---------------- HMMA GEMM: T[v] = half( [dinv[v] *] (A[v] @ W) ), fp16 in ----------------
// BM=128 rows/CTA, 256 threads (8 warps). A,W fp16 in smem, XOR-swizzled 16B chunks.
// SCALE_DINV=false for layer 1 (dinv not ready yet; agg1 applies it per edge).
template <int NOUT, bool SCALE_DINV>
__global__ void __launch_bounds__(256, 2)
gemm_mma_kernel(const __half* __restrict__ A, const __half* __restrict__ W,
                const float* __restrict__ dinv, __half* __restrict__ T) {
    extern __shared__ __align__(16) __half smem[];
    __half* sA = smem;                 // [128][128] swizzled
    __half* sW = smem + 128 * 128;     // [128][NOUT] swizzled
    constexpr int WCH = NOUT / 8;      // 16B chunks per W row
    int tid = threadIdx.x, lane = tid & 31, warp = tid >> 5;
    int row0 = blockIdx.x * 128;

    for (int i = tid; i < 128 * WCH; i += 256) {
        int r = i / WCH, cb = i % WCH;
        uint4 o = *reinterpret_cast<const uint4*>(W + (size_t)r * NOUT + cb * 8);
        int sc = cb ^ (r & 7);
        if (NOUT == 64) sc &= 7;
        *reinterpret_cast<uint4*>(sW + (size_t)r * NOUT + sc * 8) = o;
    }
    {
        int r = tid >> 1, part = tid & 1;
        int gr = row0 + r;
        bool rv = gr < N_NODES;
        #pragma unroll
        for (int j = 0; j < 8; j++) {
            int cb = part * 8 + j;
            uint4 o = rv ? *reinterpret_cast<const uint4*>(A + (size_t)gr * 128 + cb * 8)
                         : make_uint4(0u, 0u, 0u, 0u);
            *reinterpret_cast<uint4*>(sA + (size_t)r * 128 + (cb ^ (r & 7)) * 8) = o;
        }
    }
    __syncthreads();

    constexpr int NT8 = NOUT / 16;
    int wm = warp & 3, wn = warp >> 2;
    int rw = wm * 32;
    int nw = wn * (NOUT / 2);

    float acc[2][NT8][4];
    #pragma unroll
    for (int m = 0; m < 2; m++)
        #pragma unroll
        for (int j = 0; j < NT8; j++)
            #pragma unroll
            for (int q = 0; q < 4; q++) acc[m][j][q] = 0.f;

    int lrow = (lane & 7) + ((lane & 8) ? 8 : 0);
    int lcol = (lane & 16) ? 8 : 0;

    #pragma unroll
    for (int kk = 0; kk < 128; kk += 16) {
        uint32_t a[2][4];
        #pragma unroll
        for (int m = 0; m < 2; m++) {
            int r_ = rw + m * 16 + lrow;
            int c_ = kk + lcol;
            ldsm_x4(a[m][0], a[m][1], a[m][2], a[m][3],
                    smem_u32(sA + (size_t)r_ * 128 + (((c_ >> 3) ^ (r_ & 7)) << 3)));
        }
        uint32_t b[NT8][2];
        #pragma unroll
        for (int j = 0; j < NT8 / 2; j++) {
            int kr = kk + lrow;
            int nc = nw + j * 16 + lcol;
            int sc = (nc >> 3) ^ (kr & 7);
            if (NOUT == 64) sc &= 7;
            uint32_t t0, t1, t2, t3;
            ldsm_x4_t(t0, t1, t2, t3, smem_u32(sW + (size_t)kr * NOUT + (sc << 3)));
            b[2 * j][0] = t0; b[2 * j][1] = t1;
            b[2 * j + 1][0] = t2; b[2 * j + 1][1] = t3;
        }
        #pragma unroll
        for (int m = 0; m < 2; m++)
            #pragma unroll
            for (int j = 0; j < NT8; j++)
                mma16816(acc[m][j], a[m], b[j][0], b[j][1]);
    }

    #pragma unroll
    for (int m = 0; m < 2; m++) {
        int ro = rw + m * 16 + (lane >> 2);
        int r1 = row0 + ro, r2 = r1 + 8;
        float dv1 = 1.f, dv2 = 1.f;
        if (SCALE_DINV) {
            dv1 = (r1 < N_NODES) ? dinv[r1] : 0.f;
            dv2 = (r2 < N_NODES) ? dinv[r2] : 0.f;
        }
        #pragma unroll
        for (int j = 0; j < NT8; j++) {
            int c = nw + j * 8 + (lane & 3) * 2;
            if (r1 < N_NODES) {
                __half2 h = __floats2half2_rn(acc[m][j][0] * dv1, acc[m][j][1] * dv1);
                *reinterpret_cast<__half2*>(T + (size_t)r1 * NOUT + c) = h;
            }
            if (r2 < N_NODES) {
                __half2 h = __floats2half2_rn(acc[m][j][2] * dv2, acc[m][j][3] * dv2);
                *reinterpret_cast<__half2*>(T + (size_t)r2 * NOUT + c) = h;
            }
        }
    }
}

// ---------------- aggregation (fp16 in/out) ----------------
// SRC_SCALE=false: h[v] = relu(dinv[v]*(t[v] + sum t[s]) + b)          (t pre-scaled)
// SRC_SCALE=true : h[v] = relu(dinv[v]*(dinv[v]*t[v] + sum dinv[s]*t[s]) + b)  (t raw)
template <int F, bool SRC_SCALE>
__global__ void agg_kernel(const __half* __restrict__ T,
                           const int* __restrict__ off,
                           const int* __restrict__ cnt,
                           const float* __restrict__ dinv,
                           const float* __restrict__ bias,
                           __half* __restrict__ H,
                           const int* __restrict__ src) {
    constexpr int V = F / 32;
    int warp = threadIdx.x >> 5, lane = threadIdx.x & 31;
    int v = blockIdx.x * (blockDim.x >> 5) + warp;
    if (v >= N_NODES) return;
    int f0 = lane * V;
    float dv = dinv[v];
    float acc[V];
    {
        const __half* tv = T + (size_t)v * F + f0;
        float ss = SRC_SCALE ? dv : 1.0f;
        if (V == 4) {
            uint2 q = *reinterpret_cast<const uint2*>(tv);
            float2 a = __half22float2(*reinterpret_cast<const __half2*>(&q.x));
            float2 b = __half22float2(*reinterpret_cast<const __half2*>(&q.y));
            acc[0] = ss * a.x; acc[1] = ss * a.y; acc[2] = ss * b.x; acc[3] = ss * b.y;
        } else {
            uint32_t q = *reinterpret_cast<const uint32_t*>(tv);
            float2 a = __half22float2(*reinterpret_cast<const __half2*>(&q));
            acc[0] = ss * a.x; acc[1] = ss * a.y;
        }
    }
    int e0 = off[v], e1 = e0 + cnt[v];
    #pragma unroll 4
    for (int e = e0; e < e1; e++) {
        int s = src[e];
        float ds = SRC_SCALE ? dinv[s] : 1.0f;
        const __half* ts = T + (size_t)s * F + f0;
        if (V == 4) {
            uint2 q = *reinterpret_cast<const uint2*>(ts);
            float2 a = __half22float2(*reinterpret_cast<const __half2*>(&q.x));
            float2 b = __half22float2(*reinterpret_cast<const __half2*>(&q.y));
            if (SRC_SCALE) {
                acc[0] = fmaf(ds, a.x, acc[0]); acc[1] = fmaf(ds, a.y, acc[1]);
                acc[2] = fmaf(ds, b.x, acc[2]); acc[3] = fmaf(ds, b.y, acc[3]);
            } else {
                acc[0] += a.x; acc[1] += a.y; acc[2] += b.x; acc[3] += b.y;
            }
        } else {
            uint32_t q = *reinterpret_cast<const uint32_t*>(ts);
            float2 a = __half22float2(*reinterpret_cast<const __half2*>(&q));
            if (SRC_SCALE) {
                acc[0] = fmaf(ds, a.x, acc[0]); acc[1] = fmaf(ds, a.y, acc[1]);
            } else {
                acc[0] += a.x; acc[1] += a.y;
            }
        }
    }
    #pragma unroll
    for (int i = 0; i < V; i++)
        acc[i] = fmaxf(dv * acc[i] + bias[f0 + i], 0.f);
    __half* hv = H + (size_t)v * F + f0;
    if (V == 4) {
        uint2 o;
        __half2 h;
        h = __floats2half2_rn(acc[0], acc[1]); o.x = *reinterpret_cast<uint32_t*>(&h);
        h = __floats2half2_rn(acc[2], acc[3]); o.y = *reinterpret_cast<uint32_t*>(&h);
        *reinterpret_cast<uint2*>(hv) = o;
    } else {
        __half2 h = __floats2half2_rn(acc[0], acc[1]);
        *reinterpret_cast<__half2*>(hv) = h;
    }
}

// ---------------- pooling + MLP (+ cleanup of cnt/gcur for next call) ----------------
__device__ __forceinline__ int lb32(const int* __restrict__ b, int n, int key) {
    int lo = 0, hi = n;
    while (lo < hi) {
        int mid = (lo + hi) >> 1;
        if (b[mid] < key) lo = mid + 1; else hi = mid;
    }
    return lo;
}

__global__ void pool_mlp_kernel(const __half* __restrict__ H,
                                const int* __restrict__ batch,
                                const float* __restrict__ Wf1, const float* __restrict__ bf1,
                                const float* __restrict__ Wf2, const float* __restrict__ bf2,
                                float* __restrict__ out,
                                int* __restrict__ cnt, int* __restrict__ gcur) {
    __shared__ float partial[256];
    __shared__ float pooled[64];
    __shared__ float hid[32];
    int g = blockIdx.x;
    int t = threadIdx.x;
    for (int i = g * 256 + t; i < N_NODES; i += N_GRAPHS * 256) cnt[i] = 0;
    if (g == 0 && t == 0) *gcur = 0;

    int start = lb32(batch, N_NODES, g);
    int end   = lb32(batch, N_NODES, g + 1);
    int n = end - start;
    int feat = t & 63;
    int strip = t >> 6;
    float s = 0.f;
    for (int i = start + strip; i < end; i += 4)
        s += __half2float(H[(size_t)i * 64 + feat]);
    partial[t] = s;
    __syncthreads();
    if (t < 64) {
        float tot = partial[t] + partial[t + 64] + partial[t + 128] + partial[t + 192];
        pooled[t] = tot / fmaxf((float)n, 1.0f);
    }
    __syncthreads();
    if (t < 32) {
        float a = bf1[t];
        #pragma unroll 8
        for (int k = 0; k < 64; k++) a += pooled[k] * Wf1[k * 32 + t];
        hid[t] = fmaxf(a, 0.f);
    }
    __syncthreads();
    if (t < 10) {
        float a = bf2[t];
        #pragma unroll
        for (int k = 0; k < 32; k++) a += hid[k] * Wf2[k * 10 + t];
        out[g * 10 + t] = a;
    }
}

// ---------------- launch ----------------
extern "C" void kernel_launch(void* const* d_in, const int* in_sizes, int n_in,
                              void* d_out, int out_size) {
    const float* x     = (const float*)d_in[0];
    const int*   ei    = (const int*)d_in[1];     // int32 (JAX x64 disabled)
    const int*   batch = (const int*)d_in[2];
    const float* W1 = (const float*)d_in[3];
    const float* b1 = (const float*)d_in[4];
    const float* W2 = (const float*)d_in[5];
    const float* b2 = (const float*)d_in[6];
    const float* W3 = (const float*)d_in[7];
    const float* b3 = (const float*)d_in[8];
    const float* Wf1 = (const float*)d_in[9];
    const float* bf1 = (const float*)d_in[10];
    const float* Wf2 = (const float*)d_in[11];
    const float* bf2 = (const float*)d_in[12];
    float* out = (float*)d_out;

    const int* row = ei;
    const int* col = ei + N_EDGES;

    int *p_cnt, *p_off, *p_cursor, *p_src, *p_gcur;
    float *p_dinv;
    __half *p_x16, *p_w16, *p_t, *p_hh;
    cudaGetSymbolAddress((void**)&p_cnt,    d_cnt);
    cudaGetSymbolAddress((void**)&p_off,    d_off);
    cudaGetSymbolAddress((void**)&p_cursor, d_cursor);
    cudaGetSymbolAddress((void**)&p_src,    d_src);
    cudaGetSymbolAddress((void**)&p_gcur,   d_gcur);
    cudaGetSymbolAddress((void**)&p_dinv,   d_dinv);
    cudaGetSymbolAddress((void**)&p_x16,    d_x16);
    cudaGetSymbolAddress((void**)&p_w16,    d_w16);
    cudaGetSymbolAddress((void**)&p_t,      d_t);
    cudaGetSymbolAddress((void**)&p_hh,     d_hh);

    static cudaStream_t s2 = nullptr;
    static cudaEvent_t evF = nullptr, evJ = nullptr;
    if (s2 == nullptr) {
        cudaStreamCreateWithFlags(&s2, cudaStreamNonBlocking);
        cudaEventCreateWithFlags(&evF, cudaEventDisableTiming);
        cudaEventCreateWithFlags(&evJ, cudaEventDisableTiming);
    }

    const int SM128 = (128 * 128 + 128 * 128) * 2;   // 64 KB
    const int SM64  = (128 * 128 + 128 * 64) * 2;    // 48 KB
    cudaFuncSetAttribute((const void*)gemm_mma_kernel<128, false>, cudaFuncAttributeMaxDynamicSharedMemorySize, SM128);
    cudaFuncSetAttribute((const void*)gemm_mma_kernel<128, true>,  cudaFuncAttributeMaxDynamicSharedMemorySize, SM128);
    cudaFuncSetAttribute((const void*)gemm_mma_kernel<64, true>,   cudaFuncAttributeMaxDynamicSharedMemorySize, SM64);

    const int E2 = (N_EDGES / 2 + 255) / 256;
    const int GB = (N_NODES + 127) / 128;    // 391
    const int AGG_BLOCKS = (N_NODES + 7) / 8;

    // fork: CSR build on s2, concurrent with fp16 prep + gemm1 (dinv-free) on s0
    cudaEventRecord(evF, 0);
    cudaStreamWaitEvent(s2, evF, 0);
    count_kernel<<<E2, 256, 0, s2>>>(col, p_cnt);
    assign_kernel<<<(N_NODES + 1023) / 1024, 1024, 0, s2>>>(p_cnt, p_off, p_cursor, p_dinv, p_gcur);
    fill_kernel<<<E2, 256, 0, s2>>>(row, col, p_cursor, p_src);
    cudaEventRecord(evJ, s2);

    conv_x_kernel<<<(N_NODES * 128 / 8 + 255) / 256, 256>>>(x, p_x16);
    conv_w_kernel<<<160, 256>>>(W1, W2, W3, p_w16);
    gemm_mma_kernel<128, false><<<GB, 256, SM128>>>(p_x16, p_w16, p_dinv, p_t);  // raw t
    cudaStreamWaitEvent(0, evJ, 0);   // join: CSR + dinv ready
    agg_kernel<128, true><<<AGG_BLOCKS, 256>>>(p_t, p_off, p_cnt, p_dinv, b1, p_hh, p_src);
    gemm_mma_kernel<128, true><<<GB, 256, SM128>>>(p_hh, p_w16 + 16384, p_dinv, p_t);
    agg_kernel<128, false><<<AGG_BLOCKS, 256>>>(p_t, p_off, p_cnt, p_dinv, b2, p_hh, p_src);
    gemm_mma_kernel<64, true><<<GB, 256, SM64>>>(p_hh, p_w16 + 32768, p_dinv, p_t);
    agg_kernel<64, false><<<AGG_BLOCKS, 256>>>(p_t, p_off, p_cnt, p_dinv, b3, p_hh, p_src);

    pool_mlp_kernel<<<N_GRAPHS, 256>>>(p_hh, batch, Wf1, bf1, Wf2, bf2, out, p_cnt, p_gcur);
}

// round 12
// speedup vs baseline: 1.0146x; 1.0146x over previous
#include <cuda_runtime.h>
#include <cuda_fp16.h>
#include <math.h>
#include <stdint.h>

#define N_NODES 50000
#define N_EDGES 800000
#define N_GRAPHS 100

// ---------------- device scratch (no allocation allowed; 16B aligned) ----------------
__device__ __align__(16) int    d_cnt[N_NODES];      // stays 0 between calls (re-zeroed by pool_mlp)
__device__ __align__(16) float  d_dinv[N_NODES];
__device__ __align__(16) int    d_off[N_NODES];
__device__ __align__(16) int    d_cursor[N_NODES];
__device__ __align__(16) int    d_src[N_EDGES];
__device__ int d_gcur;                               // stays 0 between calls
__device__ __align__(16) __half d_x16[(size_t)N_NODES * 128]; // fp16 copy of x
__device__ __align__(16) __half d_w16[40960];                 // fp16 W1|W2|W3 images
__device__ __align__(16) __half d_t[(size_t)N_NODES * 128];   // fp16 gather buffer
__device__ __align__(16) __half d_hh[(size_t)N_NODES * 128];  // fp16 features

// ---------------- mma helpers ----------------
__device__ __forceinline__ uint32_t smem_u32(const void* p) {
    uint32_t a;
    asm("{ .reg .u64 t; cvta.to.shared.u64 t, %1; cvt.u32.u64 %0, t; }" : "=r"(a) : "l"(p));
    return a;
}
__device__ __forceinline__ void ldsm_x4(uint32_t& r0, uint32_t& r1, uint32_t& r2, uint32_t& r3,
                                        uint32_t addr) {
    asm volatile("ldmatrix.sync.aligned.m8n8.x4.shared.b16 {%0,%1,%2,%3}, [%4];"
                 : "=r"(r0), "=r"(r1), "=r"(r2), "=r"(r3) : "r"(addr));
}
__device__ __forceinline__ void ldsm_x4_t(uint32_t& r0, uint32_t& r1, uint32_t& r2, uint32_t& r3,
                                          uint32_t addr) {
    asm volatile("ldmatrix.sync.aligned.m8n8.x4.trans.shared.b16 {%0,%1,%2,%3}, [%4];"
                 : "=r"(r0), "=r"(r1), "=r"(r2), "=r"(r3) : "r"(addr));
}
__device__ __forceinline__ void mma16816(float* c, const uint32_t* a, uint32_t b0, uint32_t b1) {
    asm volatile("mma.sync.aligned.m16n8k16.row.col.f32.f16.f16.f32 "
                 "{%0,%1,%2,%3}, {%4,%5,%6,%7}, {%8,%9}, {%0,%1,%2,%3};"
                 : "+f"(c[0]), "+f"(c[1]), "+f"(c[2]), "+f"(c[3])
                 : "r"(a[0]), "r"(a[1]), "r"(a[2]), "r"(a[3]), "r"(b0), "r"(b1));
}

// ---------------- fp16 prep (x + W images, one kernel) ----------------
__global__ void prep_kernel(const float* __restrict__ x,
                            const float* __restrict__ W1, const float* __restrict__ W2,
                            const float* __restrict__ W3,
                            __half* __restrict__ x16, __half* __restrict__ w16) {
    int i = blockIdx.x * blockDim.x + threadIdx.x;
    if (i < 40960) {
        if (i < 16384)      w16[i] = __float2half_rn(W1[i]);
        else if (i < 32768) w16[i] = __float2half_rn(W2[i - 16384]);
        else                w16[i] = __float2half_rn(W3[i - 32768]);
    }
    size_t o = (size_t)i * 8;
    if (o < (size_t)N_NODES * 128) {
        float4 a0 = *reinterpret_cast<const float4*>(x + o);
        float4 a1 = *reinterpret_cast<const float4*>(x + o + 4);
        uint4 u;
        __half2 h;
        h = __floats2half2_rn(a0.x, a0.y); u.x = *reinterpret_cast<uint32_t*>(&h);
        h = __floats2half2_rn(a0.z, a0.w); u.y = *reinterpret_cast<uint32_t*>(&h);
        h = __floats2half2_rn(a1.x, a1.y); u.z = *reinterpret_cast<uint32_t*>(&h);
        h = __floats2half2_rn(a1.z, a1.w); u.w = *reinterpret_cast<uint32_t*>(&h);
        *reinterpret_cast<uint4*>(x16 + o) = u;
    }
}

// ---------------- CSR build (scan-free) ----------------
__global__ void count_kernel(const int* __restrict__ col, int* __restrict__ cnt) {
    int e2 = blockIdx.x * blockDim.x + threadIdx.x;
    int e = e2 * 2;
    if (e + 1 < N_EDGES) {
        int2 c = *reinterpret_cast<const int2*>(col + e);
        if ((unsigned)c.x < N_NODES) atomicAdd(cnt + c.x, 1);
        if ((unsigned)c.y < N_NODES) atomicAdd(cnt + c.y, 1);
    } else if (e < N_EDGES) {
        unsigned c = (unsigned)col[e];
        if (c < N_NODES) atomicAdd(cnt + c, 1);
    }
}

__global__ void assign_kernel(const int* __restrict__ cnt, int* __restrict__ off,
                              int* __restrict__ cursor, float* __restrict__ dinv,
                              int* __restrict__ gcur) {
    __shared__ int ws[32];
    __shared__ int s_base;
    int i = blockIdx.x * 1024 + threadIdx.x;
    int lane = threadIdx.x & 31, wid = threadIdx.x >> 5;
    int v = (i < N_NODES) ? cnt[i] : 0;
    int x = v;
    #pragma unroll
    for (int d = 1; d < 32; d <<= 1) {
        int y = __shfl_up_sync(0xffffffffu, x, d);
        if (lane >= d) x += y;
    }
    if (lane == 31) ws[wid] = x;
    __syncthreads();
    if (wid == 0) {
        int s = ws[lane];
        #pragma unroll
        for (int d = 1; d < 32; d <<= 1) {
            int y = __shfl_up_sync(0xffffffffu, s, d);
            if (lane >= d) s += y;
        }
        ws[lane] = s;
        if (lane == 31) s_base = atomicAdd(gcur, s);
    }
    __syncthreads();
    int excl = s_base + (wid ? ws[wid - 1] : 0) + x - v;
    if (i < N_NODES) {
        off[i] = excl;
        cursor[i] = excl;
        dinv[i] = rsqrtf((float)(v + 1));
    }
}

__global__ void fill_kernel(const int* __restrict__ row,
                            const int* __restrict__ col,
                            int* __restrict__ cursor, int* __restrict__ src) {
    int e2 = blockIdx.x * blockDim.x + threadIdx.x;
    int e = e2 * 2;
    if (e + 1 < N_EDGES) {
        int2 c = *reinterpret_cast<const int2*>(col + e);
        int2 r = *reinterpret_cast<const int2*>(row + e);
        if ((unsigned)c.x < N_NODES) {
            int pos = atomicAdd(cursor + c.x, 1);
            if ((unsigned)pos < N_EDGES) src[pos] = r.x;
        }
        if ((unsigned)c.y < N_NODES) {
            int pos = atomicAdd(cursor + c.y, 1);
            if ((unsigned)pos < N_EDGES) src[pos] = r.y;
        }
    } else if (e < N_EDGES) {
        unsigned c = (unsigned)col[e];
        if (c < N_NODES) {
            int pos = atomicAdd(cursor + c, 1);
            if ((unsigned)pos < N_EDGES) src[pos] = row[e];
        }
    }
}

// ---------------- HMMA GEMM: T[v] = half( [dinv[v] *] (A[v] @ W) ), fp16 in ----------------
template <int NOUT, bool SCALE_DINV>
__global__ void __launch_bounds__(256, 2)
gemm_mma_kernel(const __half* __restrict__ A, const __half* __restrict__ W,
                const float* __restrict__ dinv, __half* __restrict__ T) {
    extern __shared__ __align__(16) __half smem[];
    __half* sA = smem;                 // [128][128] swizzled
    __half* sW = smem + 128 * 128;     // [128][NOUT] swizzled
    constexpr int WCH = NOUT / 8;      // 16B chunks per W row
    int tid = threadIdx.x, lane = tid & 31, warp = tid >> 5;
    int row0 = blockIdx.x * 128;

    for (int i = tid; i < 128 * WCH; i += 256) {
        int r = i / WCH, cb = i % WCH;
        uint4 o = *reinterpret_cast<const uint4*>(W + (size_t)r * NOUT + cb * 8);
        int sc = cb ^ (r & 7);
        if (NOUT == 64) sc &= 7;
        *reinterpret_cast<uint4*>(sW + (size_t)r * NOUT + sc * 8) = o;
    }
    {
        int r = tid >> 1, part = tid & 1;
        int gr = row0 + r;
        bool rv = gr < N_NODES;
        #pragma unroll
        for (int j = 0; j < 8; j++) {
            int cb = part * 8 + j;
            uint4 o = rv ? *reinterpret_cast<const uint4*>(A + (size_t)gr * 128 + cb * 8)
                         : make_uint4(0u, 0u, 0u, 0u);
            *reinterpret_cast<uint4*>(sA + (size_t)r * 128 + (cb ^ (r & 7)) * 8) = o;
        }
    }
    __syncthreads();

    constexpr int NT8 = NOUT / 16;
    int wm = warp & 3, wn = warp >> 2;
    int rw = wm * 32;
    int nw = wn * (NOUT / 2);

    float acc[2][NT8][4];
    #pragma unroll
    for (int m = 0; m < 2; m++)
        #pragma unroll
        for (int j = 0; j < NT8; j++)
            #pragma unroll
            for (int q = 0; q < 4; q++) acc[m][j][q] = 0.f;

    int lrow = (lane & 7) + ((lane & 8) ? 8 : 0);
    int lcol = (lane & 16) ? 8 : 0;

    #pragma unroll
    for (int kk = 0; kk < 128; kk += 16) {
        uint32_t a[2][4];
        #pragma unroll
        for (int m = 0; m < 2; m++) {
            int r_ = rw + m * 16 + lrow;
            int c_ = kk + lcol;
            ldsm_x4(a[m][0], a[m][1], a[m][2], a[m][3],
                    smem_u32(sA + (size_t)r_ * 128 + (((c_ >> 3) ^ (r_ & 7)) << 3)));
        }
        uint32_t b[NT8][2];
        #pragma unroll
        for (int j = 0; j < NT8 / 2; j++) {
            int kr = kk + lrow;
            int nc = nw + j * 16 + lcol;
            int sc = (nc >> 3) ^ (kr & 7);
            if (NOUT == 64) sc &= 7;
            uint32_t t0, t1, t2, t3;
            ldsm_x4_t(t0, t1, t2, t3, smem_u32(sW + (size_t)kr * NOUT + (sc << 3)));
            b[2 * j][0] = t0; b[2 * j][1] = t1;
            b[2 * j + 1][0] = t2; b[2 * j + 1][1] = t3;
        }
        #pragma unroll
        for (int m = 0; m < 2; m++)
            #pragma unroll
            for (int j = 0; j < NT8; j++)
                mma16816(acc[m][j], a[m], b[j][0], b[j][1]);
    }

    #pragma unroll
    for (int m = 0; m < 2; m++) {
        int ro = rw + m * 16 + (lane >> 2);
        int r1 = row0 + ro, r2 = r1 + 8;
        float dv1 = 1.f, dv2 = 1.f;
        if (SCALE_DINV) {
            dv1 = (r1 < N_NODES) ? dinv[r1] : 0.f;
            dv2 = (r2 < N_NODES) ? dinv[r2] : 0.f;
        }
        #pragma unroll
        for (int j = 0; j < NT8; j++) {
            int c = nw + j * 8 + (lane & 3) * 2;
            if (r1 < N_NODES) {
                __half2 h = __floats2half2_rn(acc[m][j][0] * dv1, acc[m][j][1] * dv1);
                *reinterpret_cast<__half2*>(T + (size_t)r1 * NOUT + c) = h;
            }
            if (r2 < N_NODES) {
                __half2 h = __floats2half2_rn(acc[m][j][2] * dv2, acc[m][j][3] * dv2);
                *reinterpret_cast<__half2*>(T + (size_t)r2 * NOUT + c) = h;
            }
        }
    }
}

// ---------------- aggregation (fp16 in/out), multi-edge per warp iteration ----------------
// Lane group of LPE=F/8 lanes handles one edge with uint4 (8-half) loads;
// warp processes 32/LPE edges per iteration; combine via shfl_xor at the end.
// SRC_SCALE=true: t raw -> h[v]=relu(dv*(dv*t[v]+sum dinv[s]*t[s])+b); else t pre-scaled.
template <int F, bool SRC_SCALE>
__global__ void agg_kernel(const __half* __restrict__ T,
                           const int* __restrict__ off,
                           const int* __restrict__ cnt,
                           const float* __restrict__ dinv,
                           const float* __restrict__ bias,
                           __half* __restrict__ H,
                           const int* __restrict__ src) {
    constexpr int LPE = F / 8;        // lanes per edge: 16 (F=128) or 8 (F=64)
    constexpr int EPI = 32 / LPE;     // edges per iteration: 2 or 4
    int warp = threadIdx.x >> 5, lane = threadIdx.x & 31;
    int v = blockIdx.x * (blockDim.x >> 5) + warp;
    if (v >= N_NODES) return;
    int sub = lane / LPE;             // edge slot within warp
    int f0 = (lane % LPE) * 8;        // 8 halves per lane
    float dv = dinv[v];

    float acc[8];
    #pragma unroll
    for (int i = 0; i < 8; i++) acc[i] = 0.f;

    // self term (sub 0 only)
    if (sub == 0) {
        uint4 q = *reinterpret_cast<const uint4*>(T + (size_t)v * F + f0);
        float ss = SRC_SCALE ? dv : 1.0f;
        const __half2* hp = reinterpret_cast<const __half2*>(&q);
        #pragma unroll
        for (int j = 0; j < 4; j++) {
            float2 f = __half22float2(hp[j]);
            acc[2 * j]     = ss * f.x;
            acc[2 * j + 1] = ss * f.y;
        }
    }

    int e0 = off[v], e1 = e0 + cnt[v];
    for (int e = e0 + sub; e < e1; e += EPI) {
        int s = src[e];
        float ds = SRC_SCALE ? dinv[s] : 1.0f;
        uint4 q = *reinterpret_cast<const uint4*>(T + (size_t)s * F + f0);
        const __half2* hp = reinterpret_cast<const __half2*>(&q);
        #pragma unroll
        for (int j = 0; j < 4; j++) {
            float2 f = __half22float2(hp[j]);
            if (SRC_SCALE) {
                acc[2 * j]     = fmaf(ds, f.x, acc[2 * j]);
                acc[2 * j + 1] = fmaf(ds, f.y, acc[2 * j + 1]);
            } else {
                acc[2 * j]     += f.x;
                acc[2 * j + 1] += f.y;
            }
        }
    }

    // combine edge slots
    #pragma unroll
    for (int m = LPE; m < 32; m <<= 1)
        #pragma unroll
        for (int j = 0; j < 8; j++)
            acc[j] += __shfl_xor_sync(0xffffffffu, acc[j], m);

    if (sub == 0) {
        float4 b0 = *reinterpret_cast<const float4*>(bias + f0);
        float4 b1 = *reinterpret_cast<const float4*>(bias + f0 + 4);
        float bb[8] = {b0.x, b0.y, b0.z, b0.w, b1.x, b1.y, b1.z, b1.w};
        #pragma unroll
        for (int j = 0; j < 8; j++)
            acc[j] = fmaxf(fmaf(dv, acc[j], bb[j]), 0.f);
        uint4 o;
        __half2 h;
        h = __floats2half2_rn(acc[0], acc[1]); o.x = *reinterpret_cast<uint32_t*>(&h);
        h = __floats2half2_rn(acc[2], acc[3]); o.y = *reinterpret_cast<uint32_t*>(&h);
        h = __floats2half2_rn(acc[4], acc[5]); o.z = *reinterpret_cast<uint32_t*>(&h);
        h = __floats2half2_rn(acc[6], acc[7]); o.w = *reinterpret_cast<uint32_t*>(&h);
        *reinterpret_cast<uint4*>(H + (size_t)v * F + f0) = o;
    }
}

// ---------------- pooling + MLP (+ cleanup of cnt/gcur for next call) ----------------
__device__ __forceinline__ int lb32(const int* __restrict__ b, int n, int key) {
    int lo = 0, hi = n;
    while (lo < hi) {
        int mid = (lo + hi) >> 1;
        if (b[mid] < key) lo = mid + 1; else hi = mid;
    }
    return lo;
}

__global__ void pool_mlp_kernel(const __half* __restrict__ H,
                                const int* __restrict__ batch,
                                const float* __restrict__ Wf1, const float* __restrict__ bf1,
                                const float* __restrict__ Wf2, const float* __restrict__ bf2,
                                float* __restrict__ out,
                                int* __restrict__ cnt, int* __restrict__ gcur) {
    __shared__ float partial[256];
    __shared__ float pooled[64];
    __shared__ float hid[32];
    int g = blockIdx.x;
    int t = threadIdx.x;
    for (int i = g * 256 + t; i < N_NODES; i += N_GRAPHS * 256) cnt[i] = 0;
    if (g == 0 && t == 0) *gcur = 0;

    int start = lb32(batch, N_NODES, g);
    int end   = lb32(batch, N_NODES, g + 1);
    int n = end - start;
    int feat = t & 63;
    int strip = t >> 6;
    float s = 0.f;
    for (int i = start + strip; i < end; i += 4)
        s += __half2float(H[(size_t)i * 64 + feat]);
    partial[t] = s;
    __syncthreads();
    if (t < 64) {
        float tot = partial[t] + partial[t + 64] + partial[t + 128] + partial[t + 192];
        pooled[t] = tot / fmaxf((float)n, 1.0f);
    }
    __syncthreads();
    if (t < 32) {
        float a = bf1[t];
        #pragma unroll 8
        for (int k = 0; k < 64; k++) a += pooled[k] * Wf1[k * 32 + t];
        hid[t] = fmaxf(a, 0.f);
    }
    __syncthreads();
    if (t < 10) {
        float a = bf2[t];
        #pragma unroll
        for (int k = 0; k < 32; k++) a += hid[k] * Wf2[k * 10 + t];
        out[g * 10 + t] = a;
    }
}

// ---------------- launch ----------------
extern "C" void kernel_launch(void* const* d_in, const int* in_sizes, int n_in,
                              void* d_out, int out_size) {
    const float* x     = (const float*)d_in[0];
    const int*   ei    = (const int*)d_in[1];     // int32 (JAX x64 disabled)
    const int*   batch = (const int*)d_in[2];
    const float* W1 = (const float*)d_in[3];
    const float* b1 = (const float*)d_in[4];
    const float* W2 = (const float*)d_in[5];
    const float* b2 = (const float*)d_in[6];
    const float* W3 = (const float*)d_in[7];
    const float* b3 = (const float*)d_in[8];
    const float* Wf1 = (const float*)d_in[9];
    const float* bf1 = (const float*)d_in[10];
    const float* Wf2 = (const float*)d_in[11];
    const float* bf2 = (const float*)d_in[12];
    float* out = (float*)d_out;

    const int* row = ei;
    const int* col = ei + N_EDGES;

    int *p_cnt, *p_off, *p_cursor, *p_src, *p_gcur;
    float *p_dinv;
    __half *p_x16, *p_w16, *p_t, *p_hh;
    cudaGetSymbolAddress((void**)&p_cnt,    d_cnt);
    cudaGetSymbolAddress((void**)&p_off,    d_off);
    cudaGetSymbolAddress((void**)&p_cursor, d_cursor);
    cudaGetSymbolAddress((void**)&p_src,    d_src);
    cudaGetSymbolAddress((void**)&p_gcur,   d_gcur);
    cudaGetSymbolAddress((void**)&p_dinv,   d_dinv);
    cudaGetSymbolAddress((void**)&p_x16,    d_x16);
    cudaGetSymbolAddress((void**)&p_w16,    d_w16);
    cudaGetSymbolAddress((void**)&p_t,      d_t);
    cudaGetSymbolAddress((void**)&p_hh,     d_hh);

    static cudaStream_t s2 = nullptr;
    static cudaEvent_t evF = nullptr, evJ = nullptr;
    if (s2 == nullptr) {
        cudaStreamCreateWithFlags(&s2, cudaStreamNonBlocking);
        cudaEventCreateWithFlags(&evF, cudaEventDisableTiming);
        cudaEventCreateWithFlags(&evJ, cudaEventDisableTiming);
    }

    const int SM128 = (128 * 128 + 128 * 128) * 2;   // 64 KB
    const int SM64  = (128 * 128 + 128 * 64) * 2;    // 48 KB
    cudaFuncSetAttribute((const void*)gemm_mma_kernel<128, false>, cudaFuncAttributeMaxDynamicSharedMemorySize, SM128);
    cudaFuncSetAttribute((const void*)gemm_mma_kernel<128, true>,  cudaFuncAttributeMaxDynamicSharedMemorySize, SM128);
    cudaFuncSetAttribute((const void*)gemm_mma_kernel<64, true>,   cudaFuncAttributeMaxDynamicSharedMemorySize, SM64);

    const int E2 = (N_EDGES / 2 + 255) / 256;
    const int GB = (N_NODES + 127) / 128;    // 391
    const int AGG_BLOCKS = (N_NODES + 7) / 8;

    // fork: CSR build on s2, concurrent with fp16 prep + gemm1 (dinv-free) on s0
    cudaEventRecord(evF, 0);
    cudaStreamWaitEvent(s2, evF, 0);
    count_kernel<<<E2, 256, 0, s2>>>(col, p_cnt);                                      // slot 1
    assign_kernel<<<(N_NODES + 1023) / 1024, 1024, 0, s2>>>(p_cnt, p_off, p_cursor, p_dinv, p_gcur); // 2
    fill_kernel<<<E2, 256, 0, s2>>>(row, col, p_cursor, p_src);                        // 3
    cudaEventRecord(evJ, s2);

    prep_kernel<<<(N_NODES * 128 / 8 + 255) / 256, 256>>>(x, W1, W2, W3, p_x16, p_w16); // 4
    gemm_mma_kernel<128, false><<<GB, 256, SM128>>>(p_x16, p_w16, p_dinv, p_t);        // 5
    cudaStreamWaitEvent(0, evJ, 0);   // join: CSR + dinv ready
    agg_kernel<128, true><<<AGG_BLOCKS, 256>>>(p_t, p_off, p_cnt, p_dinv, b1, p_hh, p_src);   // 6 <- ncu
    gemm_mma_kernel<128, true><<<GB, 256, SM128>>>(p_hh, p_w16 + 16384, p_dinv, p_t);
    agg_kernel<128, false><<<AGG_BLOCKS, 256>>>(p_t, p_off, p_cnt, p_dinv, b2, p_hh, p_src);
    gemm_mma_kernel<64, true><<<GB, 256, SM64>>>(p_hh, p_w16 + 32768, p_dinv, p_t);
    agg_kernel<64, false><<<AGG_BLOCKS, 256>>>(p_t, p_off, p_cnt, p_dinv, b3, p_hh, p_src);

    pool_mlp_kernel<<<N_GRAPHS, 256>>>(p_hh, batch, Wf1, bf1, Wf2, bf2, out, p_cnt, p_gcur);
}